// round 5
// baseline (speedup 1.0000x reference)
#include <cuda_runtime.h>
#include <math.h>

#define B  8
#define C  64
#define Hc 256
#define Wc 256
#define CR 128
#define HR 128
#define WR 128

__device__ float g_scores[B * CR];
__device__ int   g_idx[B * C];

// ---------------------------------------------------------------------------
// Kernel 1: analytic upsample-mean score. Single front batch of 16 float4
// loads per thread (MLP 16), 4 independent accumulators.
// ---------------------------------------------------------------------------
__global__ void __launch_bounds__(256) scores_kernel(const float* __restrict__ readout) {
    __shared__ float wA[HR];
    __shared__ float red[8];
    const int tid = threadIdx.x;

    if (tid < HR) wA[tid] = 0.0f;
    __syncthreads();
    {
        const float cst = (float)(127.0 / 255.0);
        float pos = (float)tid * cst;
        int i0 = (int)pos;
        if (i0 > HR - 2) i0 = HR - 2;
        float w = pos - (float)i0;
        atomicAdd(&wA[i0], 1.0f - w);
        atomicAdd(&wA[i0 + 1], w);
    }
    __syncthreads();

    const int plane = blockIdx.x;
    const float4* __restrict__ src =
        (const float4*)(readout + (size_t)plane * (HR * WR));

    float4 v[16];
    #pragma unroll
    for (int j = 0; j < 16; j++)
        v[j] = src[tid + j * 256];

    float acc0 = 0.f, acc1 = 0.f, acc2 = 0.f, acc3 = 0.f;
    #pragma unroll
    for (int j = 0; j < 16; j++) {
        int base = (tid + j * 256) << 2;
        int row = base >> 7;
        int col = base & 127;
        float wr = wA[row];
        float s = wA[col] * v[j].x + wA[col + 1] * v[j].y +
                  wA[col + 2] * v[j].z + wA[col + 3] * v[j].w;
        int lane = j & 3;
        if (lane == 0) acc0 += wr * s;
        else if (lane == 1) acc1 += wr * s;
        else if (lane == 2) acc2 += wr * s;
        else acc3 += wr * s;
    }

    float acc = (acc0 + acc1) + (acc2 + acc3);
    #pragma unroll
    for (int s = 16; s > 0; s >>= 1)
        acc += __shfl_down_sync(0xffffffffu, acc, s);
    if ((tid & 31) == 0) red[tid >> 5] = acc;
    __syncthreads();
    if (tid == 0) {
        float t = 0.f;
        #pragma unroll
        for (int w2 = 0; w2 < 8; w2++) t += red[w2];
        g_scores[plane] = t * (1.0f / (float)(Hc * Wc));
    }
}

// ---------------------------------------------------------------------------
// Kernel 2: per-batch descending bitonic sort of 128 scores (tie: lower idx
// first, matching jax.lax.top_k). Writes top C=64 indices.
// ---------------------------------------------------------------------------
__global__ void topk_kernel() {
    __shared__ float sv[CR];
    __shared__ int   si[CR];
    const int tid = threadIdx.x;
    const int b = blockIdx.x;

    sv[tid] = g_scores[b * CR + tid];
    si[tid] = tid;
    __syncthreads();

    for (int k = 2; k <= CR; k <<= 1) {
        for (int j = k >> 1; j > 0; j >>= 1) {
            int ixj = tid ^ j;
            if (ixj > tid) {
                float va = sv[tid], vb = sv[ixj];
                int   ia = si[tid], ib = si[ixj];
                bool first = (va > vb) || (va == vb && ia < ib);
                bool ascSeg = ((tid & k) == 0);
                bool doSwap = ascSeg ? (!first) : first;
                if (doSwap) {
                    sv[tid] = vb; sv[ixj] = va;
                    si[tid] = ib; si[ixj] = ia;
                }
            }
            __syncthreads();
        }
    }

    if (tid < C) g_idx[b * C + tid] = si[tid];
}

// ---------------------------------------------------------------------------
// Kernel 3: fused bilinear-upsample + gated blend, WARP-AUTONOMOUS.
// Block = 16 output rows x 256 cols (256 threads). Each warp owns 2 output
// rows, stages its own 3 readout rows into a private smem slice, and syncs
// only with __syncwarp(). 7 front-batched LDGs per lane, 4 streamed stores.
// ---------------------------------------------------------------------------
__global__ void __launch_bounds__(256) fuse_kernel(
    const float* __restrict__ x,
    const float* __restrict__ readout,
    const float* __restrict__ weight,
    const float* __restrict__ bias,
    float* __restrict__ out)
{
    __shared__ float srow[8 * 3 * WR];   // 3 rows per warp

    const int plane = blockIdx.z;
    const int b = plane >> 6;
    const int c = plane & (C - 1);
    const int ch = g_idx[plane];

    const float* __restrict__ rsrc =
        readout + ((size_t)b * CR + ch) * (HR * WR);

    const int tid = threadIdx.x;
    const int w   = tid >> 5;             // warp 0..7
    const int l   = tid & 31;             // lane

    const int y0 = (blockIdx.y << 4) + (w << 1);   // this warp's first row
    const float cst = (float)(127.0 / 255.0);

    // source rows needed by rows y0, y0+1: [iy_a, iy_a+2] (clamped)
    int iy_a = (int)((float)y0 * cst);
    if (iy_a > HR - 2) iy_a = HR - 2;

    float* __restrict__ ws = srow + w * (3 * WR);

    // ---- front-batched stage loads: 3 rows x 128 floats = 3 float4/lane ----
    float4 sv[3];
    int srcrow[3];
    #pragma unroll
    for (int r = 0; r < 3; r++) {
        int rr = iy_a + r;
        if (rr > HR - 1) rr = HR - 1;
        srcrow[r] = rr;
        sv[r] = __ldg((const float4*)(rsrc + rr * WR + (l << 2)));
    }

    // ---- front-batched x loads: 2 rows x 2 float4/lane (dense) ----
    const size_t obase = ((size_t)plane * Hc + y0) * Wc;
    float4 xv[4];
    size_t oofs[4];
    #pragma unroll
    for (int r = 0; r < 2; r++) {
        oofs[2 * r]     = obase + (size_t)r * Wc + (l << 2);
        oofs[2 * r + 1] = obase + (size_t)r * Wc + (l << 2) + 128;
        xv[2 * r]     = __ldcs((const float4*)(x + oofs[2 * r]));
        xv[2 * r + 1] = __ldcs((const float4*)(x + oofs[2 * r + 1]));
    }

    #pragma unroll
    for (int r = 0; r < 3; r++)
        *(float4*)(ws + r * WR + (l << 2)) = sv[r];
    __syncwarp();

    const float w0 = __ldg(weight + 2 * c);
    const float w1 = __ldg(weight + 2 * c + 1);
    const float bs = __ldg(bias + c);

    #pragma unroll
    for (int r = 0; r < 2; r++) {
        const int y = y0 + r;
        float posy = (float)y * cst;
        int iy0 = (int)posy;
        if (iy0 > HR - 2) iy0 = HR - 2;
        const float wy  = posy - (float)iy0;
        const float wy0 = 1.0f - wy;

        const float* __restrict__ s0 = ws + (iy0 - iy_a) * WR;
        const float* __restrict__ s1 = s0 + WR;

        #pragma unroll
        for (int h = 0; h < 2; h++) {           // two float4 per row
            const int x0 = (l << 2) + h * 128;
            float4 xq = xv[2 * r + h];
            float xs[4] = {xq.x, xq.y, xq.z, xq.w};
            float os[4];
            #pragma unroll
            for (int k = 0; k < 4; k++) {
                float posx = (float)(x0 + k) * cst;
                int ix0 = (int)posx;
                if (ix0 > WR - 2) ix0 = WR - 2;
                float wx = posx - (float)ix0;
                // reference order: interpolate H first, then W
                float a  = s0[ix0]     * wy0 + s1[ix0]     * wy;
                float bb = s0[ix0 + 1] * wy0 + s1[ix0 + 1] * wy;
                float rv = a * (1.0f - wx) + bb * wx;
                float t = xs[k] * w0 + rv * w1 + bs;
                float gate = 1.0f / (1.0f + __expf(-t));
                os[k] = xs[k] + gate * (rv - xs[k]);
            }
            __stcs((float4*)(out + oofs[2 * r + h]),
                   make_float4(os[0], os[1], os[2], os[3]));
        }
    }
    (void)srcrow;
}

// ---------------------------------------------------------------------------
extern "C" void kernel_launch(void* const* d_in, const int* in_sizes, int n_in,
                              void* d_out, int out_size)
{
    const float* x       = (const float*)d_in[0];
    const float* readout = (const float*)d_in[1];
    const float* weight  = (const float*)d_in[2];
    const float* bias    = (const float*)d_in[3];
    float* out = (float*)d_out;

    scores_kernel<<<B * CR, 256>>>(readout);
    topk_kernel<<<B, CR>>>();

    dim3 blk(256, 1, 1);
    dim3 grd(1, Hc / 16, B * C);   // 8192 blocks
    fuse_kernel<<<grd, blk>>>(x, readout, weight, bias, out);
}